// round 7
// baseline (speedup 1.0000x reference)
#include <cuda_runtime.h>
#include <cuda_bf16.h>
#include <cstdint>

typedef unsigned long long ull;

#define NN   10000
#define TT   64
#define NIN  64
#define NH   128
#define NOUT 64
#define KTOT 192
#define EMAX 160000
#define MTILE 32
#define GRID_GG 313            // ceil(10000/32)
#define GG_SMEM 90112          // A 24KB + B 2x32KB
#define PX_BLOCKS 80000        // TT*NN/8

// ---------------- device scratch ----------------
__device__ float d_dinv[NN];
__device__ int   d_deg[NN];
__device__ int   d_off[NN + 1];
__device__ int   d_fill[NN];
__device__ int   d_adj[EMAX];
__device__ __nv_bfloat16 d_Pxh[(size_t)TT * NN * NIN];
__device__ __nv_bfloat16 d_Pxl[(size_t)TT * NN * NIN];
__device__ float d_h[NN * NH];
__device__ float d_c[NN * NH];
__device__ float d_hs[NN * NH];
__device__ __nv_bfloat16 d_Wpk[2 * 3 * 512 * 64];  // [split][chunk][n=j*4+g][k64]
__device__ float d_bpk[512];                        // [j*4+g]
__device__ float d_W1p[NH * 256];
__device__ float d_Wcp[NH * NOUT];
__device__ float d_HaHb[NN * 256];
__device__ float d_nodes[NN * NH];
__device__ float d_Pn[NN * NH];

// ---------------- helpers ----------------
__device__ __forceinline__ uint32_t smem_u32(const void* p) {
    uint32_t a;
    asm("{ .reg .u64 t; cvta.to.shared.u64 t, %1; cvt.u32.u64 %0, t; }" : "=r"(a) : "l"(p));
    return a;
}
__device__ __forceinline__ uint32_t pkbf(__nv_bfloat16 a, __nv_bfloat16 b) {
    return (uint32_t)__bfloat16_as_ushort(a) | ((uint32_t)__bfloat16_as_ushort(b) << 16);
}
__device__ __forceinline__ void cp16(uint32_t dst, const void* src, uint32_t srcsize) {
    asm volatile("cp.async.ca.shared.global [%0], [%1], 16, %2;"
                 :: "r"(dst), "l"(src), "r"(srcsize) : "memory");
}
__device__ __forceinline__ void cp_commit() {
    asm volatile("cp.async.commit_group;" ::: "memory");
}
__device__ __forceinline__ void cp_wait1() {
    asm volatile("cp.async.wait_group 1;" ::: "memory");
}
__device__ __forceinline__ void ldsm4(uint32_t* r, uint32_t addr) {
    asm volatile("ldmatrix.sync.aligned.m8n8.x4.shared.b16 {%0,%1,%2,%3}, [%4];"
                 : "=r"(r[0]), "=r"(r[1]), "=r"(r[2]), "=r"(r[3]) : "r"(addr));
}
__device__ __forceinline__ void mma16816(float* c, const uint32_t* a, const uint32_t* b) {
    asm volatile("mma.sync.aligned.m16n8k16.row.col.f32.bf16.bf16.f32 "
                 "{%0,%1,%2,%3}, {%4,%5,%6,%7}, {%8,%9}, {%0,%1,%2,%3};"
                 : "+f"(c[0]), "+f"(c[1]), "+f"(c[2]), "+f"(c[3])
                 : "r"(a[0]), "r"(a[1]), "r"(a[2]), "r"(a[3]), "r"(b[0]), "r"(b[1]));
}
__device__ __forceinline__ float sigf(float x) { return 1.0f / (1.0f + __expf(-x)); }

// ---------------- setup kernels ----------------
__global__ void k_init() {
    int i = blockIdx.x * blockDim.x + threadIdx.x;
    if (i < NN * NH) { d_c[i] = 0.f; d_hs[i] = 0.f; }
    if (i < NN)      { d_deg[i] = 1; d_fill[i] = 0; }
}

__global__ void k_deg(const int* __restrict__ dst, int E) {
    int i = blockIdx.x * blockDim.x + threadIdx.x;
    if (i < E) atomicAdd(&d_deg[dst[i]], 1);
}

// scan (CSR offsets) + dinv in one kernel
__global__ void k_scan(int E) {
    __shared__ int ssum[1024];
    int tid = threadIdx.x;
    int loc[10]; int run = 0;
#pragma unroll
    for (int i = 0; i < 10; i++) {
        int v = tid * 10 + i;
        int c = (v < NN) ? (d_deg[v] - 1) : 0;
        loc[i] = run; run += c;
    }
    ssum[tid] = run; __syncthreads();
    for (int off = 1; off < 1024; off <<= 1) {
        int t = (tid >= off) ? ssum[tid - off] : 0;
        __syncthreads();
        ssum[tid] += t;
        __syncthreads();
    }
    int base = (tid == 0) ? 0 : ssum[tid - 1];
#pragma unroll
    for (int i = 0; i < 10; i++) {
        int v = tid * 10 + i;
        if (v < NN) {
            d_off[v] = base + loc[i];
            d_dinv[v] = rsqrtf((float)d_deg[v]);
        }
    }
    if (tid == 0) d_off[NN] = E;
}

__global__ void k_fill(const int* __restrict__ src, const int* __restrict__ dst, int E) {
    int i = blockIdx.x * blockDim.x + threadIdx.x;
    if (i < E) {
        int v = dst[i];
        int p = d_off[v] + atomicAdd(&d_fill[v], 1);
        d_adj[p] = src[i];
    }
}

// fused: blocks < PX_BLOCKS compute Px (bf16 hi/lo split); tail blocks pack weights
#define WPK_N   196608
#define BPK_END (WPK_N + 512)
#define W1P_END (BPK_END + NH * 256)
#define WCP_END (W1P_END + NH * NOUT)
__global__ void k_pxpack(const float* __restrict__ x,
                         const float* __restrict__ Wi, const float* __restrict__ bi,
                         const float* __restrict__ Wf, const float* __restrict__ bf,
                         const float* __restrict__ Wo, const float* __restrict__ bo,
                         const float* __restrict__ Wg, const float* __restrict__ bg,
                         const float* __restrict__ W1, const float* __restrict__ Wc) {
    if (blockIdx.x < PX_BLOCKS) {
        int w = blockIdx.x * 8 + (threadIdx.x >> 5);
        int t = w / NN, v = w - t * NN;
        int l2 = (threadIdx.x & 31) * 2;
        const float* xt = x + (size_t)t * NN * NIN;
        float2 a = make_float2(0.f, 0.f);
        int e = d_off[v], end = d_off[v + 1];
#pragma unroll 4
        for (; e < end; e++) {
            int s = d_adj[e];
            float ds = d_dinv[s];
            float2 xv = *(const float2*)&xt[s * NIN + l2];
            a.x += ds * xv.x; a.y += ds * xv.y;
        }
        float dv = d_dinv[v];
        float2 xs = *(const float2*)&xt[v * NIN + l2];
        a.x = dv * (a.x + dv * xs.x);
        a.y = dv * (a.y + dv * xs.y);
        __nv_bfloat16 h0 = __float2bfloat16(a.x), h1 = __float2bfloat16(a.y);
        __nv_bfloat16 l0 = __float2bfloat16(a.x - __bfloat162float(h0));
        __nv_bfloat16 l1 = __float2bfloat16(a.y - __bfloat162float(h1));
        size_t o = ((size_t)t * NN + v) * NIN + l2;
        *(uint32_t*)&d_Pxh[o] = pkbf(h0, h1);
        *(uint32_t*)&d_Pxl[o] = pkbf(l0, l1);
    } else {
        int idx = (blockIdx.x - PX_BLOCKS) * 256 + threadIdx.x;
        if (idx < WPK_N) {
            int s = idx / 98304;
            int r = idx % 98304;
            int c = r / 32768; r %= 32768;
            int n = r / 64;    int kk = r % 64;
            int j = n >> 2, g = n & 3, k = c * 64 + kk;
            const float* W = (g == 0) ? Wi : (g == 1) ? Wf : (g == 2) ? Wo : Wg;
            float w = W[j * KTOT + k];
            __nv_bfloat16 hi = __float2bfloat16(w);
            d_Wpk[idx] = (s == 0) ? hi : __float2bfloat16(w - __bfloat162float(hi));
        } else if (idx < BPK_END) {
            int i = idx - WPK_N;
            int j = i >> 2, g = i & 3;
            const float* b = (g == 0) ? bi : (g == 1) ? bf : (g == 2) ? bo : bg;
            d_bpk[i] = b[j];
        } else if (idx < W1P_END) {
            int r = idx - BPK_END;
            int k = r / 256, cc = r % 256;
            d_W1p[r] = W1[(cc & 127) * 256 + (cc >> 7) * 128 + k];
        } else if (idx < WCP_END) {
            int r = idx - W1P_END;
            int k = r / NOUT, j = r % NOUT;
            d_Wcp[r] = Wc[j * NH + k];
        }
    }
}

// ---------------- fused step kernel: prop + 3-pass bf16-split GEMM + LSTM ------
// B stage st (0..11): c = st>>2 (K chunk), kh = (st>>1)&1 (k32 half), sb = st&1
__device__ __forceinline__ void gg_loadB(uint32_t dstbase, int st, int tid) {
    int c = st >> 2, kh = (st >> 1) & 1, sbw = st & 1;
    const __nv_bfloat16* Bg = d_Wpk + ((size_t)(sbw * 3 + c) * 512) * 64 + kh * 32;
#pragma unroll
    for (int it = 0; it < 8; it++) {
        int idx = tid + it * 256;
        int n = idx >> 2, kg = idx & 3;
        cp16(dstbase + n * 64 + ((kg ^ ((n >> 1) & 3)) << 4), Bg + (size_t)n * 64 + kg * 8, 16);
    }
}

__device__ __forceinline__ void gg_pass(float (&acc)[2][8][4], uint32_t sA_tile,
                                        int kh, int ks, const uint32_t (&bfr)[4][4],
                                        int g, int lr) {
    uint32_t af[2][4];
#pragma unroll
    for (int mt = 0; mt < 2; mt++) {
        int arow = mt * 16 + (g & 1) * 8 + lr;
        int akg = kh * 4 + ks * 2 + (g >> 1);
        ldsm4(af[mt], sA_tile + arow * 128 + ((akg ^ (arow & 7)) << 4));
    }
#pragma unroll
    for (int mt = 0; mt < 2; mt++)
#pragma unroll
        for (int nt = 0; nt < 8; nt++)
            mma16816(acc[mt][nt], af[mt], &bfr[nt >> 1][(nt & 1) * 2]);
}

__global__ void __launch_bounds__(256, 2) k_gg(int t, int last) {
    extern __shared__ char smem[];
    const uint32_t sb = smem_u32(smem);
    const int tid = threadIdx.x, lane = tid & 31, wid = tid >> 5;
    const int m0 = blockIdx.x * MTILE;
    const int wn = wid * 64;
    const int g = lane >> 3, lr = lane & 7;
    const uint32_t BBASE = 24576;

    // issue A c=0 (Px hi/lo) + B stage 0  -> group 0
    {
        int row = tid >> 3, kg = tid & 7;
        uint32_t soff = row * 128 + ((kg ^ (row & 7)) << 4);
        size_t go = ((size_t)t * NN + m0 + row) * 64 + kg * 8;
        uint32_t ok = (m0 + row < NN) ? 16 : 0;
        cp16(sb + 0 * 4096 + soff, d_Pxh + go, ok);   // A(s=0,c=0)
        cp16(sb + 3 * 4096 + soff, d_Pxl + go, ok);   // A(s=1,c=0)
    }
    gg_loadB(sb + BBASE, 0, tid);
    cp_commit();
    gg_loadB(sb + BBASE + 32768, 1, tid);
    cp_commit();

    // prop phase: Ph for own 32 rows, split to bf16, store into A(s,1)/A(s,2)
#pragma unroll
    for (int i = 0; i < 4; i++) {
        int rl = wid * 4 + i;
        int m = m0 + rl;
        if (m < NN) {
            int f4 = lane * 4;
            float4 a = *(const float4*)&d_hs[m * NH + f4];
            int e = d_off[m], end = d_off[m + 1];
            for (; e + 1 < end; e += 2) {
                int s0 = d_adj[e], s1 = d_adj[e + 1];
                float4 v0 = *(const float4*)&d_hs[s0 * NH + f4];
                float4 v1 = *(const float4*)&d_hs[s1 * NH + f4];
                a.x += v0.x + v1.x; a.y += v0.y + v1.y;
                a.z += v0.z + v1.z; a.w += v0.w + v1.w;
            }
            if (e < end) {
                int s0 = d_adj[e];
                float4 v0 = *(const float4*)&d_hs[s0 * NH + f4];
                a.x += v0.x; a.y += v0.y; a.z += v0.z; a.w += v0.w;
            }
            float dv = d_dinv[m];
            a.x *= dv; a.y *= dv; a.z *= dv; a.w *= dv;
            __nv_bfloat16 h0 = __float2bfloat16(a.x), h1 = __float2bfloat16(a.y);
            __nv_bfloat16 h2 = __float2bfloat16(a.z), h3 = __float2bfloat16(a.w);
            __nv_bfloat16 l0 = __float2bfloat16(a.x - __bfloat162float(h0));
            __nv_bfloat16 l1 = __float2bfloat16(a.y - __bfloat162float(h1));
            __nv_bfloat16 l2 = __float2bfloat16(a.z - __bfloat162float(h2));
            __nv_bfloat16 l3 = __float2bfloat16(a.w - __bfloat162float(h3));
            uint32_t hi01 = pkbf(h0, h1);
            uint32_t hi23 = pkbf(h2, h3);
            uint32_t lo01 = pkbf(l0, l1);
            uint32_t lo23 = pkbf(l2, l3);
            int ci = 1 + (f4 >> 6);
            int kk = f4 & 63;
            uint32_t off = rl * 128 + (((kk >> 3) ^ (rl & 7)) << 4) + (kk & 7) * 2;
            *(uint2*)(smem + ci * 4096 + off)       = make_uint2(hi01, hi23);
            *(uint2*)(smem + (3 + ci) * 4096 + off) = make_uint2(lo01, lo23);
        }
    }

    float acc[2][8][4];
#pragma unroll
    for (int i = 0; i < 2; i++)
#pragma unroll
        for (int j = 0; j < 8; j++)
#pragma unroll
            for (int q = 0; q < 4; q++) acc[i][j][q] = 0.f;

    // 12 pipelined B stages; sb=0 stage feeds passes hi*hi and lo*hi
    for (int st = 0; st < 12; st++) {
        cp_wait1();
        __syncthreads();
        uint32_t sB = sb + BBASE + (st & 1) * 32768;
        int c = st >> 2, kh = (st >> 1) & 1;
#pragma unroll
        for (int ks = 0; ks < 2; ks++) {
            uint32_t bfr[4][4];
#pragma unroll
            for (int nsub = 0; nsub < 4; nsub++) {
                int brow = wn + nsub * 16 + (g >> 1) * 8 + lr;
                int bkg = ks * 2 + (g & 1);
                ldsm4(bfr[nsub], sB + brow * 64 + ((bkg ^ ((brow >> 1) & 3)) << 4));
            }
            gg_pass(acc, sb + c * 4096, kh, ks, bfr, g, lr);          // sa=0
            if (!(st & 1))
                gg_pass(acc, sb + (3 + c) * 4096, kh, ks, bfr, g, lr); // sa=1
        }
        __syncthreads();
        if (st + 2 < 12) gg_loadB(sb + BBASE + (st & 1) * 32768, st + 2, tid);
        cp_commit();
    }

    // stage accumulators to smem (reuse A/B area), then fused LSTM epilogue
    float* Cs = (float*)smem;
#pragma unroll
    for (int mt = 0; mt < 2; mt++)
#pragma unroll
        for (int nt = 0; nt < 8; nt++) {
            int r = mt * 16 + (lane >> 2);
            int col = wn + nt * 8 + (lane & 3) * 2;
            *(float2*)&Cs[r * 516 + col]       = make_float2(acc[mt][nt][0], acc[mt][nt][1]);
            *(float2*)&Cs[(r + 8) * 516 + col] = make_float2(acc[mt][nt][2], acc[mt][nt][3]);
        }
    __syncthreads();

#pragma unroll
    for (int it = 0; it < 16; it++) {
        int idx = it * 256 + tid;
        int mloc = idx >> 7, jloc = idx & 127;
        int m = m0 + mloc;
        if (m >= NN) continue;
        float4 pre = *(const float4*)&Cs[mloc * 516 + jloc * 4];
        float4 bb = *(const float4*)&d_bpk[jloc * 4];
        float i_ = sigf(pre.x + bb.x);
        float f_ = sigf(pre.y + bb.y);
        float o_ = sigf(pre.z + bb.z);
        float g_ = tanhf(pre.w + bb.w);
        int ci = m * NH + jloc;
        float cn = f_ * d_c[ci] + i_ * g_;
        float hh = o_ * tanhf(cn);
        d_c[ci] = cn;
        d_hs[ci] = d_dinv[m] * hh;
        if (last) d_h[ci] = hh;
    }
}

// ---------------- decoder ----------------
__global__ void k_gemm(int sel, const float* __restrict__ bias, float* __restrict__ Cout,
                       int M, int K, int N) {
    __shared__ __align__(16) float As[16][64];
    __shared__ __align__(16) float Bs[16][64];
    const float* A = sel ? d_Pn  : d_h;
    const float* B = sel ? d_Wcp : d_W1p;
    float*       C = sel ? Cout  : d_HaHb;
    int tid = threadIdx.x;
    int tx = tid & 15, ty = tid >> 4;
    int m0 = blockIdx.x * 64, n0 = blockIdx.y * 64;
    float acc[4][4] = {};
    int lrow = tid >> 2, lkp = (tid & 3) * 4;
    int bk = tid >> 4, bcc = (tid & 15) * 4;
    for (int kc = 0; kc < K; kc += 16) {
        float4 av = make_float4(0.f, 0.f, 0.f, 0.f);
        int grow = m0 + lrow;
        if (grow < M) av = *(const float4*)&A[grow * K + kc + lkp];
        As[lkp + 0][lrow] = av.x; As[lkp + 1][lrow] = av.y;
        As[lkp + 2][lrow] = av.z; As[lkp + 3][lrow] = av.w;
        float4 bv = *(const float4*)&B[(kc + bk) * N + n0 + bcc];
        *(float4*)&Bs[bk][bcc] = bv;
        __syncthreads();
#pragma unroll
        for (int k = 0; k < 16; k++) {
            float4 a = *(const float4*)&As[k][ty * 4];
            float4 b = *(const float4*)&Bs[k][tx * 4];
            float ar[4] = {a.x, a.y, a.z, a.w};
            float br[4] = {b.x, b.y, b.z, b.w};
#pragma unroll
            for (int i = 0; i < 4; i++)
#pragma unroll
                for (int j = 0; j < 4; j++) acc[i][j] = fmaf(ar[i], br[j], acc[i][j]);
        }
        __syncthreads();
    }
    float4 bb = make_float4(0.f, 0.f, 0.f, 0.f);
    if (bias) bb = *(const float4*)&bias[n0 + tx * 4];
#pragma unroll
    for (int i = 0; i < 4; i++) {
        int m = m0 + ty * 4 + i;
        if (m >= M) continue;
        float4 o = make_float4(acc[i][0] + bb.x, acc[i][1] + bb.y,
                               acc[i][2] + bb.z, acc[i][3] + bb.w);
        *(float4*)&C[m * N + n0 + tx * 4] = o;
    }
}

__global__ void k_edge_nodes(const float* __restrict__ b1) {
    int w = blockIdx.x * 8 + (threadIdx.x >> 5);
    if (w >= NN) return;
    int l4 = (threadIdx.x & 31) * 4;
    float4 ha = *(const float4*)&d_HaHb[w * 256 + l4];
    float4 bb = *(const float4*)&b1[l4];
    ha.x += bb.x; ha.y += bb.y; ha.z += bb.z; ha.w += bb.w;
    float4 acc = make_float4(0.f, 0.f, 0.f, 0.f);
    int e = d_off[w], end = d_off[w + 1];
#pragma unroll 2
    for (; e < end; e++) {
        int s = d_adj[e];
        float4 hb = *(const float4*)&d_HaHb[s * 256 + 128 + l4];
        acc.x += fmaxf(ha.x + hb.x, 0.f);
        acc.y += fmaxf(ha.y + hb.y, 0.f);
        acc.z += fmaxf(ha.z + hb.z, 0.f);
        acc.w += fmaxf(ha.w + hb.w, 0.f);
    }
    *(float4*)&d_nodes[w * NH + l4] = acc;
}

__global__ void k_prop2() {
    int w = blockIdx.x * 8 + (threadIdx.x >> 5);
    if (w >= NN) return;
    int l4 = (threadIdx.x & 31) * 4;
    float dv = d_dinv[w];
    float4 sv = *(const float4*)&d_nodes[w * NH + l4];
    float4 acc = make_float4(dv * sv.x, dv * sv.y, dv * sv.z, dv * sv.w);
    int e = d_off[w], end = d_off[w + 1];
#pragma unroll 2
    for (; e < end; e++) {
        int s = d_adj[e];
        float ds = d_dinv[s];
        float4 v0 = *(const float4*)&d_nodes[s * NH + l4];
        acc.x += ds * v0.x; acc.y += ds * v0.y;
        acc.z += ds * v0.z; acc.w += ds * v0.w;
    }
    acc.x *= dv; acc.y *= dv; acc.z *= dv; acc.w *= dv;
    *(float4*)&d_Pn[w * NH + l4] = acc;
}

// ---------------- host launcher ----------------
extern "C" void kernel_launch(void* const* d_in, const int* in_sizes, int n_in,
                              void* d_out, int out_size) {
    const float* x  = (const float*)d_in[0];
    const int*   ei = (const int*)d_in[1];
    const int    E  = in_sizes[2];
    const int* src = ei;
    const int* dst = ei + E;
    const float* Wi = (const float*)d_in[4];
    const float* bi = (const float*)d_in[5];
    const float* Wf = (const float*)d_in[6];
    const float* bf = (const float*)d_in[7];
    const float* Wo = (const float*)d_in[8];
    const float* bo = (const float*)d_in[9];
    const float* Wg = (const float*)d_in[10];
    const float* bg = (const float*)d_in[11];
    const float* W1 = (const float*)d_in[12];
    const float* b1 = (const float*)d_in[13];
    const float* Wc = (const float*)d_in[14];
    const float* bc = (const float*)d_in[15];
    float* out = (float*)d_out;

    static int smem_set = 0;
    if (!smem_set) {
        cudaFuncSetAttribute(k_gg, cudaFuncAttributeMaxDynamicSharedMemorySize, GG_SMEM);
        smem_set = 1;
    }

    int packBlocks = (WCP_END + 255) / 256;
    k_init<<<(NN * NH + 255) / 256, 256>>>();
    k_deg<<<(E + 255) / 256, 256>>>(dst, E);
    k_scan<<<1, 1024>>>(E);
    k_fill<<<(E + 255) / 256, 256>>>(src, dst, E);
    k_pxpack<<<PX_BLOCKS + packBlocks, 256>>>(x, Wi, bi, Wf, bf, Wo, bo, Wg, bg, W1, Wc);

    for (int t = 0; t < TT; t++)
        k_gg<<<GRID_GG, 256, GG_SMEM>>>(t, t == TT - 1);

    k_gemm<<<dim3((NN + 63) / 64, 4), 256>>>(0, nullptr, nullptr, NN, NH, 256);
    k_edge_nodes<<<NN / 8, 256>>>(b1);
    k_prop2<<<NN / 8, 256>>>();
    k_gemm<<<dim3((NN + 63) / 64, 1), 256>>>(1, bc, out, NN, NH, NOUT);
}